// round 7
// baseline (speedup 1.0000x reference)
#include <cuda_runtime.h>
#include <cuda_fp16.h>
#include <cstddef>

// Problem constants (match reference_code)
#define T_STEPS 600
#define N_REC   5000
#define N_IN    100
#define N_OUT   100
#define NR4     1250   // N_REC / 4 (float4 units)
#define NR4P    1280   // padded float4 count for r staging (covers fp16 pad)
#define HPAD    5120   // fp16 row stride in halves (= 320 x 16-half units)
#define HUNITS  320    // 32-byte units per padded fp16 row

#define WARPS    24
#define PTHREADS (WARPS * 32)   // 768
#define P_PIN    10             // fp32 W rows pinned in SMEM per block (200 KB)

// Scratch (allocation-free rule: __device__ globals)
__device__ float    g_x[N_REC];
__device__ float    g_drive[(size_t)T_STEPS * N_REC];
__device__ unsigned g_bar;                       // grid barrier counter
__device__ unsigned g_w16[(size_t)N_REC * (HPAD / 2)]; // streamed W rows, fp16 pairs (51.2 MB)

__device__ __forceinline__ unsigned ld_acq(const unsigned* p) {
    unsigned v;
    asm volatile("ld.global.acquire.gpu.u32 %0, [%1];" : "=r"(v) : "l"(p));
    return v;
}

// 256-bit evict_last load of 16 fp16 values (8 half2 words)
__device__ __forceinline__ void ldg_h16(const unsigned* p, unsigned* h) {
    asm("ld.global.nc.L2::evict_last.v8.b32 {%0,%1,%2,%3,%4,%5,%6,%7}, [%8];"
        : "=r"(h[0]), "=r"(h[1]), "=r"(h[2]), "=r"(h[3]),
          "=r"(h[4]), "=r"(h[5]), "=r"(h[6]), "=r"(h[7])
        : "l"(p));
}

// ---------------------------------------------------------------------------
// init: hidden[0] = r, x = arctanh(r), reset grid barrier
// ---------------------------------------------------------------------------
__global__ void init_kernel(const float* __restrict__ r, float* __restrict__ hidden) {
    int i = blockIdx.x * blockDim.x + threadIdx.x;
    if (i == 0) g_bar = 0u;
    if (i < N_REC) {
        float rv = r[i];
        hidden[i] = rv;
        g_x[i] = atanhf(rv);
    }
}

// ---------------------------------------------------------------------------
// convert streamed W rows (row >= pin_total) to fp16, padded to HPAD halves
// ---------------------------------------------------------------------------
__global__ __launch_bounds__(256) void conv_kernel(
    const float* __restrict__ W, int pin_total, int n_stream)
{
    int e = blockIdx.x * blockDim.x + threadIdx.x;     // one half2 pair each
    int total = n_stream * (HPAD / 2);
    if (e >= total) return;
    int sidx = e / (HPAD / 2);
    int p    = e % (HPAD / 2);
    int k    = 2 * p;
    const float* src = W + (size_t)(pin_total + sidx) * N_REC;
    float a = (k     < N_REC) ? src[k]     : 0.0f;
    float b = (k + 1 < N_REC) ? src[k + 1] : 0.0f;
    __half2 h = __floats2half2_rn(a, b);
    g_w16[(size_t)sidx * (HPAD / 2) + p] = *(unsigned*)&h;
}

// ---------------------------------------------------------------------------
// drive[t][i] = sum_k u[t][k] * W_in[i][k] + eps[t][i]
// ---------------------------------------------------------------------------
#define DRIVE_TT 25
__global__ __launch_bounds__(128) void drive_kernel(
    const float* __restrict__ u, const float* __restrict__ W_in,
    const float* __restrict__ eps)
{
    __shared__ float us[DRIVE_TT][N_IN];
    int i  = blockIdx.x * 128 + threadIdx.x;
    int t0 = blockIdx.y * DRIVE_TT;

    for (int idx = threadIdx.x; idx < DRIVE_TT * N_IN; idx += 128) {
        int tl = idx / N_IN, k = idx % N_IN;
        us[tl][k] = u[(size_t)(t0 + tl) * N_IN + k];
    }
    __syncthreads();
    if (i >= N_REC) return;

    const float* __restrict__ Wr = W_in + (size_t)i * N_IN;
    for (int tl = 0; tl < DRIVE_TT; ++tl) {
        float acc = 0.0f;
        #pragma unroll 4
        for (int k = 0; k < N_IN; ++k)
            acc += __ldg(Wr + k) * us[tl][k];
        int t = t0 + tl;
        g_drive[(size_t)t * N_REC + i] = acc + eps[(size_t)t * N_REC + i];
    }
}

__device__ __forceinline__ float warp_reduce(float s) {
    #pragma unroll
    for (int o = 16; o; o >>= 1) s += __shfl_xor_sync(0xffffffffu, s, o);
    return s;
}

// streamed row (fp16, padded): 10 x 32B loads per lane, pad contributes 0
__device__ __forceinline__ float dot_stream16(const unsigned* __restrict__ Wr,
                                              const float4* __restrict__ rs, int lane) {
    float4 a0 = make_float4(0.f,0.f,0.f,0.f), a1 = make_float4(0.f,0.f,0.f,0.f);
    #pragma unroll
    for (int i = 0; i < 10; ++i) {
        int u = lane + (i << 5);               // 32-byte unit, 0..319
        unsigned h[8];
        ldg_h16(Wr + u * 8, h);
        const float4* rp = rs + 4 * u;         // float4 idx 4u..4u+3 (< NR4P)
        #pragma unroll
        for (int q = 0; q < 4; ++q) {
            float2 wlo = __half22float2(*(const __half2*)&h[2*q]);
            float2 whi = __half22float2(*(const __half2*)&h[2*q+1]);
            float4 rv = rp[q];
            if (q & 1) {
                a1.x += wlo.x * rv.x; a1.y += wlo.y * rv.y;
                a1.z += whi.x * rv.z; a1.w += whi.y * rv.w;
            } else {
                a0.x += wlo.x * rv.x; a0.y += wlo.y * rv.y;
                a0.z += whi.x * rv.z; a0.w += whi.y * rv.w;
            }
        }
    }
    float s = ((a0.x+a1.x)+(a0.y+a1.y)) + ((a0.z+a1.z)+(a0.w+a1.w));
    return warp_reduce(s);
}

// pinned row: W fp32 from smem, r from smem
__device__ __forceinline__ float dot_pin(const float4* __restrict__ Wp,
                                         const float4* __restrict__ rs, int lane) {
    float4 a0 = make_float4(0.f,0.f,0.f,0.f), a1 = make_float4(0.f,0.f,0.f,0.f);
    #pragma unroll 13
    for (int i = 0; i < 39; ++i) {             // float4 idx 0..1247
        int idx = lane + (i << 5);
        float4 w = Wp[idx], rv = rs[idx];
        if (i & 1) { a1.x += w.x*rv.x; a1.y += w.y*rv.y; a1.z += w.z*rv.z; a1.w += w.w*rv.w; }
        else       { a0.x += w.x*rv.x; a0.y += w.y*rv.y; a0.z += w.z*rv.z; a0.w += w.w*rv.w; }
    }
    int idx = lane + (39 << 5);                // 1248..1249 -> lanes 0,1
    if (idx < NR4) {
        float4 w = Wp[idx], rv = rs[idx];
        a0.x += w.x*rv.x; a0.y += w.y*rv.y; a0.z += w.z*rv.z; a0.w += w.w*rv.w;
    }
    float s = ((a0.x+a1.x)+(a0.y+a1.y)) + ((a0.z+a1.z)+(a0.w+a1.w));
    return warp_reduce(s);
}

// ---------------------------------------------------------------------------
// Persistent RNN rollout: one block per SM, all 600 steps in one kernel.
//   - P_PIN fp32 rows pinned in SMEM per block.
//   - remaining rows streamed as fp16 (36 MB -> L2-resident with evict_last).
//   - 220 KB smem -> occupancy 1, grid == #SMs -> single wave, barrier safe.
// ---------------------------------------------------------------------------
__global__ __launch_bounds__(PTHREADS, 1) void rnn_persistent(
    float* __restrict__ hidden, const float* __restrict__ W,
    int G, int pin_total, int n_stream)
{
    extern __shared__ float sm[];
    float4* rs   = (float4*)sm;           // [NR4P] r_prev staging (20480 B)
    float*  Wpin = sm + 4 * NR4P;         // P_PIN rows x N_REC floats (200000 B)

    const int b    = blockIdx.x;
    const int tid  = threadIdx.x;
    const int warp = tid >> 5;
    const int lane = tid & 31;

    // zero the r padding once (never overwritten: staging writes < NR4)
    if (tid < NR4P - NR4)
        rs[NR4 + tid] = make_float4(0.f, 0.f, 0.f, 0.f);

    // one-time copy of this block's pinned rows into SMEM
    {
        const float4* src = (const float4*)(W + (size_t)b * P_PIN * N_REC);
        float4* dst = (float4*)Wpin;
        for (int i = tid; i < P_PIN * NR4; i += PTHREADS) dst[i] = src[i];
    }

    const int nrows = P_PIN + (n_stream - b + G - 1) / G;

    for (int t = 0; t < T_STEPS; ++t) {
        const float4* rg = (const float4*)(hidden + (size_t)t * N_REC);
        for (int i = tid; i < NR4; i += PTHREADS) rs[i] = rg[i];
        __syncthreads();

        // high->low locals: streamed (long-latency) rows issue first
        if (warp < nrows) {
            int local = warp + WARPS * ((nrows - 1 - warp) / WARPS);
            for (; local >= 0; local -= WARPS) {
                int   row;
                float s;
                if (local < P_PIN) {
                    row = b * P_PIN + local;
                    s = dot_pin((const float4*)(Wpin + (size_t)local * N_REC), rs, lane);
                } else {
                    int sidx = b + (local - P_PIN) * G;
                    row = pin_total + sidx;
                    s = dot_stream16(g_w16 + (size_t)sidx * (HPAD / 2), rs, lane);
                }
                float x = g_x[row];
                x = 0.9f * x + 0.1f * (s + g_drive[(size_t)t * N_REC + row]);
                if (lane == 0) {
                    g_x[row] = x;
                    hidden[(size_t)(t + 1) * N_REC + row] = tanhf(x);
                }
            }
        }
        __syncthreads();

        if (tid == 0) {
            __threadfence();
            atomicAdd(&g_bar, 1u);
            unsigned tgt = (unsigned)G * (unsigned)(t + 1);
            while (ld_acq(&g_bar) < tgt) __nanosleep(64);
        }
        __syncthreads();
    }
}

// ---------------------------------------------------------------------------
// out v2: o[t][j] = sum_i hidden[t+1][i] * W_out[j][i]
//   grid=300 (2 t's each), 512 threads: 4800 warps, ~12 dots/warp (was 50).
// ---------------------------------------------------------------------------
#define OUT_OT 2
__global__ __launch_bounds__(512) void out_kernel(
    const float* __restrict__ hidden, const float* __restrict__ W_out,
    float* __restrict__ o)
{
    __shared__ float4 rsh[OUT_OT][NR4];
    int tid = threadIdx.x;
    int t0  = blockIdx.x * OUT_OT;

    for (int i = tid; i < OUT_OT * NR4; i += 512) {
        int tl = i / NR4, v = i % NR4;
        rsh[tl][v] = ((const float4*)(hidden + (size_t)(t0 + tl + 1) * N_REC))[v];
    }
    __syncthreads();

    int w    = tid >> 5;
    int lane = tid & 31;

    for (int task = w; task < N_OUT * OUT_OT; task += 16) {
        int j  = task >> 1;
        int tl = task & 1;
        const float4* __restrict__ Wr = (const float4*)(W_out + (size_t)j * N_REC);
        const float4* __restrict__ rr = rsh[tl];

        float4 a = make_float4(0.f, 0.f, 0.f, 0.f);
        #pragma unroll 8
        for (int v = lane; v < NR4; v += 32) {
            float4 wv = __ldg(Wr + v);
            float4 rv = rr[v];
            a.x += wv.x * rv.x;
            a.y += wv.y * rv.y;
            a.z += wv.z * rv.z;
            a.w += wv.w * rv.w;
        }
        float s = warp_reduce((a.x + a.y) + (a.z + a.w));
        if (lane == 0) o[(size_t)(t0 + tl) * N_OUT + j] = s;
    }
}

// ---------------------------------------------------------------------------
// kernel_launch (graph-capturable, allocation-free)
// Inputs: 0:u [600,100] 1:r [5000] 2:W_in [5000,100] 3:W_rec [5000,5000]
//         4:W_out [100,5000] 5:eps [600,5000]
// Output: hidden_states [601,5000] then o [600,100]
// ---------------------------------------------------------------------------
extern "C" void kernel_launch(void* const* d_in, const int* in_sizes, int n_in,
                              void* d_out, int out_size)
{
    const float* u     = (const float*)d_in[0];
    const float* r     = (const float*)d_in[1];
    const float* W_in  = (const float*)d_in[2];
    const float* W_rec = (const float*)d_in[3];
    const float* W_out = (const float*)d_in[4];
    const float* eps   = (const float*)d_in[5];

    float* hidden = (float*)d_out;                          // [601, 5000]
    float* o      = hidden + (size_t)(T_STEPS + 1) * N_REC; // [600, 100]

    int dev = 0, sms = 148;
    cudaGetDevice(&dev);
    cudaDeviceGetAttribute(&sms, cudaDevAttrMultiProcessorCount, dev);
    int G = sms;
    if (G < 1) G = 1;
    if (G * P_PIN > N_REC) G = N_REC / P_PIN;               // safety clamp
    const int pin_total = G * P_PIN;
    const int n_stream  = N_REC - pin_total;

    const size_t shbytes = (size_t)(4 * NR4P + P_PIN * N_REC) * sizeof(float); // 220480
    cudaFuncSetAttribute(rnn_persistent,
                         cudaFuncAttributeMaxDynamicSharedMemorySize, (int)shbytes);

    init_kernel<<<(N_REC + 255) / 256, 256>>>(r, hidden);

    const int conv_elems = n_stream * (HPAD / 2);
    conv_kernel<<<(conv_elems + 255) / 256, 256>>>(W_rec, pin_total, n_stream);

    dim3 dgrid((N_REC + 127) / 128, T_STEPS / DRIVE_TT);
    drive_kernel<<<dgrid, 128>>>(u, W_in, eps);

    rnn_persistent<<<G, PTHREADS, shbytes>>>(hidden, W_rec, G, pin_total, n_stream);

    out_kernel<<<T_STEPS / OUT_OT, 512>>>(hidden, W_out, o);
}